// round 6
// baseline (speedup 1.0000x reference)
#include <cuda_runtime.h>
#include <cuda_fp16.h>
#include <cstdint>

#define N_NODES 100000
#define IN_C    128
#define HID_C   64
#define OUT_C   32
#define E_MAX   1600000

// ---------------- scratch ----------------
__device__ float g_dinv[N_NODES];
__device__ int   g_cnt[N_NODES];
__device__ int   g_rp[N_NODES + 1];
__device__ int   g_wptr[N_NODES];
__device__ float2 g_epk[E_MAX];                       // (src bits, weight)
__device__ unsigned g_h1h[(size_t)N_NODES * 32];      // h1 fp16x2 (64 ch)
__device__ unsigned g_o1h[(size_t)N_NODES * 32];      // relu(agg1) fp16x2 (64 ch)
__device__ unsigned g_h2h[(size_t)N_NODES * 16];      // h2 fp16x2 (32 ch)

// ---------------- degree count ----------------
__global__ void k_count(const int* __restrict__ dst, int E) {
    int i = blockIdx.x * blockDim.x + threadIdx.x;
    if (i < E) atomicAdd(&g_cnt[dst[i]], 1);
}

// ---------------- monolithic scan: one block, 1024 threads ---------------
// thread t owns cnt[t*100 .. t*100+99]; also computes dinv.
__global__ void __launch_bounds__(1024) k_scan(int E) {
    __shared__ int sh[1024];
    const int t = threadIdx.x;
    const int base = t * 100;
    int s = 0;
    if (base < N_NODES) {
#pragma unroll 5
        for (int i = 0; i < 100; i += 4) {
            int4 v = *(const int4*)&g_cnt[base + i];
            s += v.x + v.y + v.z + v.w;
        }
    }
    sh[t] = s;
    __syncthreads();
#pragma unroll
    for (int off = 1; off < 1024; off <<= 1) {
        int x = (t >= off) ? sh[t - off] : 0;
        __syncthreads();
        sh[t] += x;
        __syncthreads();
    }
    int run = sh[t] - s;                    // exclusive prefix
    if (base < N_NODES) {
#pragma unroll 5
        for (int i = 0; i < 100; i += 4) {
            int idx = base + i;
            int4 cv = *(const int4*)&g_cnt[idx];
            g_dinv[idx + 0] = rsqrtf(1.0f + (float)cv.x);
            g_dinv[idx + 1] = rsqrtf(1.0f + (float)cv.y);
            g_dinv[idx + 2] = rsqrtf(1.0f + (float)cv.z);
            g_dinv[idx + 3] = rsqrtf(1.0f + (float)cv.w);
            int4 r;
            r.x = run;
            r.y = r.x + cv.x;
            r.z = r.y + cv.y;
            r.w = r.z + cv.z;
            run = r.w + cv.w;
            *(int4*)&g_rp[idx]   = r;
            *(int4*)&g_wptr[idx] = r;
        }
    }
    if (t == 0) g_rp[N_NODES] = E;
}

// ---------------- fill CSR payload ----------------
__global__ void k_fill(const int* __restrict__ src, const int* __restrict__ dst, int E) {
    int e = blockIdx.x * blockDim.x + threadIdx.x;
    if (e >= E) return;
    int s = src[e], d = dst[e];
    int pos = atomicAdd(&g_wptr[d], 1);
    g_epk[pos] = make_float2(__int_as_float(s), g_dinv[s] * g_dinv[d]);
}

// ---------------- GEMM1: h1[N,64] = x[N,128] @ W1[128,64] -> fp16 --------
#define XT_STRIDE 132
__global__ void __launch_bounds__(256) k_gemm1(const float* __restrict__ x,
                                               const float* __restrict__ W) {
    __shared__ float xs_t[32 * XT_STRIDE];
    __shared__ float ws[32 * 64];
    const int t    = threadIdx.x;
    const int row0 = blockIdx.x * 128;
    const int tx8  = (t & 7) * 8;
    const int ty4  = (t >> 3) * 4;

    unsigned long long acc[4][4];
#pragma unroll
    for (int r = 0; r < 4; ++r)
#pragma unroll
        for (int j = 0; j < 4; ++j) acc[r][j] = 0ull;

    for (int kc = 0; kc < 128; kc += 32) {
        __syncthreads();
        {
            const float4* Wv = (const float4*)(W + kc * 64);
            float4* wsv = (float4*)ws;
            wsv[t]       = Wv[t];
            wsv[t + 256] = Wv[t + 256];
        }
#pragma unroll
        for (int i = 0; i < 4; ++i) {
            int idx = t + i * 256;
            int r = idx >> 3;
            int q = idx & 7;
            float4 v;
            if (row0 + r < N_NODES)
                v = *(const float4*)(x + (size_t)(row0 + r) * IN_C + kc + q * 4);
            else
                v = make_float4(0.f, 0.f, 0.f, 0.f);
            xs_t[(q * 4 + 0) * XT_STRIDE + r] = v.x;
            xs_t[(q * 4 + 1) * XT_STRIDE + r] = v.y;
            xs_t[(q * 4 + 2) * XT_STRIDE + r] = v.z;
            xs_t[(q * 4 + 3) * XT_STRIDE + r] = v.w;
        }
        __syncthreads();

#pragma unroll 8
        for (int k = 0; k < 32; ++k) {
            float4 av = *(const float4*)&xs_t[k * XT_STRIDE + ty4];
            ulonglong2 b0 = *(const ulonglong2*)&ws[k * 64 + tx8];
            ulonglong2 b1 = *(const ulonglong2*)&ws[k * 64 + tx8 + 4];
            unsigned long long pa[4];
            asm("mov.b64 %0, {%1,%1};" : "=l"(pa[0]) : "f"(av.x));
            asm("mov.b64 %0, {%1,%1};" : "=l"(pa[1]) : "f"(av.y));
            asm("mov.b64 %0, {%1,%1};" : "=l"(pa[2]) : "f"(av.z));
            asm("mov.b64 %0, {%1,%1};" : "=l"(pa[3]) : "f"(av.w));
#pragma unroll
            for (int r = 0; r < 4; ++r) {
                asm("fma.rn.f32x2 %0, %1, %2, %0;" : "+l"(acc[r][0]) : "l"(pa[r]), "l"(b0.x));
                asm("fma.rn.f32x2 %0, %1, %2, %0;" : "+l"(acc[r][1]) : "l"(pa[r]), "l"(b0.y));
                asm("fma.rn.f32x2 %0, %1, %2, %0;" : "+l"(acc[r][2]) : "l"(pa[r]), "l"(b1.x));
                asm("fma.rn.f32x2 %0, %1, %2, %0;" : "+l"(acc[r][3]) : "l"(pa[r]), "l"(b1.y));
            }
        }
    }

#pragma unroll
    for (int r = 0; r < 4; ++r) {
        int row = row0 + ty4 + r;
        if (row < N_NODES) {
            float o[8];
#pragma unroll
            for (int j = 0; j < 4; ++j)
                asm("mov.b64 {%0,%1}, %2;" : "=f"(o[2 * j]), "=f"(o[2 * j + 1]) : "l"(acc[r][j]));
            unsigned u[4];
#pragma unroll
            for (int j = 0; j < 4; ++j) {
                __half2 hh = __floats2half2_rn(o[2 * j], o[2 * j + 1]);
                u[j] = *(unsigned*)&hh;
            }
            *(uint4*)&g_h1h[(size_t)row * 32 + (t & 7) * 4] =
                make_uint4(u[0], u[1], u[2], u[3]);
        }
    }
}

// ---------------- aggregate layer 1: full warp/node, unroll 8 ------------
__global__ void __launch_bounds__(256) k_agg1(const float* __restrict__ b1) {
    int node = blockIdx.x * 8 + (threadIdx.x >> 5);
    if (node >= N_NODES) return;
    int lane = threadIdx.x & 31;
    int beg = g_rp[node], end = g_rp[node + 1];
    float d = g_dinv[node];
    float dd = d * d;

    unsigned sp = g_h1h[(unsigned)node * 32u + lane];
    float2 sv = __half22float2(*(__half2*)&sp);
    float2 bb = *(const float2*)&b1[lane * 2];
    float ax = bb.x + sv.x * dd;
    float ay = bb.y + sv.y * dd;

    int j = beg;
    if ((j & 1) && j < end) {
        float2 p = g_epk[j];
        unsigned v = g_h1h[(unsigned)__float_as_int(p.x) * 32u + lane];
        float2 f = __half22float2(*(__half2*)&v);
        ax += p.y * f.x; ay += p.y * f.y;
        ++j;
    }
    for (; j + 7 < end; j += 8) {
        float4 e0 = *(const float4*)&g_epk[j];
        float4 e1 = *(const float4*)&g_epk[j + 2];
        float4 e2 = *(const float4*)&g_epk[j + 4];
        float4 e3 = *(const float4*)&g_epk[j + 6];
        unsigned v0 = g_h1h[(unsigned)__float_as_int(e0.x) * 32u + lane];
        unsigned v1 = g_h1h[(unsigned)__float_as_int(e0.z) * 32u + lane];
        unsigned v2 = g_h1h[(unsigned)__float_as_int(e1.x) * 32u + lane];
        unsigned v3 = g_h1h[(unsigned)__float_as_int(e1.z) * 32u + lane];
        unsigned v4 = g_h1h[(unsigned)__float_as_int(e2.x) * 32u + lane];
        unsigned v5 = g_h1h[(unsigned)__float_as_int(e2.z) * 32u + lane];
        unsigned v6 = g_h1h[(unsigned)__float_as_int(e3.x) * 32u + lane];
        unsigned v7 = g_h1h[(unsigned)__float_as_int(e3.z) * 32u + lane];
        float2 f0 = __half22float2(*(__half2*)&v0);
        float2 f1 = __half22float2(*(__half2*)&v1);
        float2 f2 = __half22float2(*(__half2*)&v2);
        float2 f3 = __half22float2(*(__half2*)&v3);
        float2 f4 = __half22float2(*(__half2*)&v4);
        float2 f5 = __half22float2(*(__half2*)&v5);
        float2 f6 = __half22float2(*(__half2*)&v6);
        float2 f7 = __half22float2(*(__half2*)&v7);
        ax += e0.y * f0.x + e0.w * f1.x + e1.y * f2.x + e1.w * f3.x
            + e2.y * f4.x + e2.w * f5.x + e3.y * f6.x + e3.w * f7.x;
        ay += e0.y * f0.y + e0.w * f1.y + e1.y * f2.y + e1.w * f3.y
            + e2.y * f4.y + e2.w * f5.y + e3.y * f6.y + e3.w * f7.y;
    }
    for (; j + 1 < end; j += 2) {
        float4 e0 = *(const float4*)&g_epk[j];
        unsigned v0 = g_h1h[(unsigned)__float_as_int(e0.x) * 32u + lane];
        unsigned v1 = g_h1h[(unsigned)__float_as_int(e0.z) * 32u + lane];
        float2 f0 = __half22float2(*(__half2*)&v0);
        float2 f1 = __half22float2(*(__half2*)&v1);
        ax += e0.y * f0.x + e0.w * f1.x;
        ay += e0.y * f0.y + e0.w * f1.y;
    }
    if (j < end) {
        float2 p = g_epk[j];
        unsigned v = g_h1h[(unsigned)__float_as_int(p.x) * 32u + lane];
        float2 f = __half22float2(*(__half2*)&v);
        ax += p.y * f.x; ay += p.y * f.y;
    }

    __half2 hh = __floats2half2_rn(fmaxf(ax, 0.f), fmaxf(ay, 0.f));
    g_o1h[(unsigned)node * 32u + lane] = *(unsigned*)&hh;
}

// ---------------- GEMM2: h2[N,32] = o1[N,64] @ W2[64,32] -> fp16 ---------
__global__ void __launch_bounds__(256) k_gemm2(const float* __restrict__ W) {
    __shared__ float xs[64 * 64];
    __shared__ float ws[64 * 32];
    const int tid  = threadIdx.x;
    const int row0 = blockIdx.x * 64;

    const float4* Wv  = (const float4*)W;
    float4*       wsv = (float4*)ws;
#pragma unroll
    for (int i = 0; i < 2; ++i) wsv[tid + i * 256] = Wv[tid + i * 256];

    int nrows = N_NODES - row0; if (nrows > 64) nrows = 64;
    for (int i = tid; i < nrows * 8; i += 256) {
        int r = i >> 3, q = i & 7;
        uint4 v = *(const uint4*)&g_o1h[(size_t)(row0 + r) * 32 + q * 4];
        float2 f0 = __half22float2(*(__half2*)&v.x);
        float2 f1 = __half22float2(*(__half2*)&v.y);
        float2 f2 = __half22float2(*(__half2*)&v.z);
        float2 f3 = __half22float2(*(__half2*)&v.w);
        float* p = &xs[r * 64 + q * 8];
        *(float4*)p       = make_float4(f0.x, f0.y, f1.x, f1.y);
        *(float4*)(p + 4) = make_float4(f2.x, f2.y, f3.x, f3.y);
    }
    __syncthreads();

    const int tx = tid & 7;
    const int ty = tid >> 3;
    const int c  = tx * 4;
    float acc[2][4] = {};
#pragma unroll 4
    for (int k = 0; k < 64; ++k) {
        float4 b = *(const float4*)&ws[k * 32 + c];
#pragma unroll
        for (int i = 0; i < 2; ++i) {
            float a = xs[(ty * 2 + i) * 64 + k];
            acc[i][0] += a * b.x; acc[i][1] += a * b.y;
            acc[i][2] += a * b.z; acc[i][3] += a * b.w;
        }
    }
#pragma unroll
    for (int i = 0; i < 2; ++i) {
        int r = row0 + ty * 2 + i;
        if (r < N_NODES) {
            __half2 h0 = __floats2half2_rn(acc[i][0], acc[i][1]);
            __half2 h1 = __floats2half2_rn(acc[i][2], acc[i][3]);
            *(uint2*)&g_h2h[(size_t)r * 16 + tx * 2] =
                make_uint2(*(unsigned*)&h0, *(unsigned*)&h1);
        }
    }
}

// ---------------- aggregate layer 2 (half-warp/edge, unroll 2) -> out ----
__global__ void __launch_bounds__(256) k_agg2(const float* __restrict__ b2,
                                              float* __restrict__ out) {
    int node = blockIdx.x * 8 + (threadIdx.x >> 5);
    if (node >= N_NODES) return;
    int lane = threadIdx.x & 31;
    int c  = lane & 15;
    int eo = lane >> 4;

    int beg = g_rp[node], end = g_rp[node + 1];
    float ax = 0.f, ay = 0.f;

    int j = beg + eo;
    for (; j + 3 < end; j += 4) {
        float2 p0 = g_epk[j];
        float2 p1 = g_epk[j + 2];
        unsigned v0 = g_h2h[(unsigned)__float_as_int(p0.x) * 16u + c];
        unsigned v1 = g_h2h[(unsigned)__float_as_int(p1.x) * 16u + c];
        float2 f0 = __half22float2(*(__half2*)&v0);
        float2 f1 = __half22float2(*(__half2*)&v1);
        ax += p0.y * f0.x + p1.y * f1.x;
        ay += p0.y * f0.y + p1.y * f1.y;
    }
    for (; j < end; j += 2) {
        float2 p = g_epk[j];
        unsigned v = g_h2h[(unsigned)__float_as_int(p.x) * 16u + c];
        float2 f = __half22float2(*(__half2*)&v);
        ax += p.y * f.x; ay += p.y * f.y;
    }

    ax += __shfl_xor_sync(0xffffffffu, ax, 16);
    ay += __shfl_xor_sync(0xffffffffu, ay, 16);

    if (eo == 0) {
        float d = g_dinv[node];
        float dd = d * d;
        unsigned sp = g_h2h[(unsigned)node * 16u + c];
        float2 sv = __half22float2(*(__half2*)&sp);
        float2 bb = *(const float2*)&b2[c * 2];
        ax += bb.x + sv.x * dd;
        ay += bb.y + sv.y * dd;
        *(float2*)&out[(size_t)node * OUT_C + c * 2] = make_float2(ax, ay);
    }
}

// ---------------- launch: fork gemm1 parallel to CSR chain ---------------
extern "C" void kernel_launch(void* const* d_in, const int* in_sizes, int n_in,
                              void* d_out, int out_size) {
    const float* x  = (const float*)d_in[0];
    const int*   ei = (const int*)  d_in[1];
    const float* W1 = (const float*)d_in[2];
    const float* b1 = (const float*)d_in[3];
    const float* W2 = (const float*)d_in[4];
    const float* b2 = (const float*)d_in[5];
    float*       out = (float*)d_out;

    const int E   = in_sizes[1] / 2;
    const int* src = ei;
    const int* dst = ei + E;

    // lazily-created side stream + events (same captured work every call)
    static cudaStream_t s2 = nullptr;
    static cudaEvent_t  evFork = nullptr, evJoin = nullptr;
    if (!s2) {
        cudaStreamCreateWithFlags(&s2, cudaStreamNonBlocking);
        cudaEventCreateWithFlags(&evFork, cudaEventDisableTiming);
        cudaEventCreateWithFlags(&evJoin, cudaEventDisableTiming);
    }

    void* cnt_ptr = nullptr;
    cudaGetSymbolAddress(&cnt_ptr, g_cnt);

    // fork: gemm1 runs concurrent with the CSR build chain
    cudaEventRecord(evFork, 0);
    cudaStreamWaitEvent(s2, evFork, 0);
    k_gemm1<<<(N_NODES + 127) / 128, 256, 0, s2>>>(x, W1);
    cudaEventRecord(evJoin, s2);

    // CSR chain on the captured (default) stream
    cudaMemsetAsync(cnt_ptr, 0, sizeof(int) * N_NODES, 0);
    k_count<<<(E + 255) / 256, 256>>>(dst, E);
    k_scan <<<1, 1024>>>(E);
    k_fill <<<(E + 255) / 256, 256>>>(src, dst, E);

    // join: agg1 needs both h1 (s2) and CSR (s0)
    cudaStreamWaitEvent(0, evJoin, 0);
    k_agg1 <<<(N_NODES + 7) / 8, 256>>>(b1);
    k_gemm2<<<(N_NODES + 63) / 64, 256>>>(W2);
    k_agg2 <<<(N_NODES + 7) / 8, 256>>>(b2, out);
}

// round 8
// speedup vs baseline: 2.2433x; 2.2433x over previous
#include <cuda_runtime.h>
#include <cuda_fp16.h>
#include <cstdint>

#define N_NODES 100000
#define IN_C    128
#define HID_C   64
#define OUT_C   32
#define E_MAX   1600000
#define NB_SCAN ((N_NODES + 255) / 256)   // 391

// ---------------- scratch ----------------
__device__ float g_dinv[N_NODES];
__device__ int   g_cnt[N_NODES];
__device__ int   g_rp[N_NODES + 1];
__device__ int   g_wptr[N_NODES];
__device__ int   g_bsum[NB_SCAN];
__device__ int   g_esrc[E_MAX];                       // CSR payload: src index only
__device__ unsigned g_h1h[(size_t)N_NODES * 32];      // h1 fp16x2 (64 ch)
__device__ unsigned g_o1h[(size_t)N_NODES * 32];      // relu(agg1) fp16x2 (64 ch)
__device__ unsigned g_h2h[(size_t)N_NODES * 16];      // h2 fp16x2 (32 ch)

// ---------------- degree / CSR ----------------
__global__ void k_zero() {
    int i = blockIdx.x * blockDim.x + threadIdx.x;
    if (i < N_NODES) g_cnt[i] = 0;
}

__global__ void k_count(const int* __restrict__ dst, int E) {
    int e0 = (blockIdx.x * blockDim.x + threadIdx.x) * 4;
    if (e0 + 3 < E) {
        int4 d4 = *(const int4*)(dst + e0);
        atomicAdd(&g_cnt[d4.x], 1);
        atomicAdd(&g_cnt[d4.y], 1);
        atomicAdd(&g_cnt[d4.z], 1);
        atomicAdd(&g_cnt[d4.w], 1);
    } else {
        for (int e = e0; e < E; ++e) atomicAdd(&g_cnt[dst[e]], 1);
    }
}

__global__ void k_scan1() {
    __shared__ int sh[256];
    int t = threadIdx.x;
    int i = blockIdx.x * 256 + t;
    int v = (i < N_NODES) ? g_cnt[i] : 0;
    if (i < N_NODES) g_dinv[i] = rsqrtf(1.0f + (float)v);
    sh[t] = v;
    __syncthreads();
#pragma unroll
    for (int off = 1; off < 256; off <<= 1) {
        int x = (t >= off) ? sh[t - off] : 0;
        __syncthreads();
        sh[t] += x;
        __syncthreads();
    }
    if (i < N_NODES) g_rp[i] = sh[t] - v;
    if (t == 255) g_bsum[blockIdx.x] = sh[255];
}

__global__ void k_scan2() {
    __shared__ int sh[512];
    int t = threadIdx.x;
    int v = (t < NB_SCAN) ? g_bsum[t] : 0;
    sh[t] = v;
    __syncthreads();
#pragma unroll
    for (int off = 1; off < 512; off <<= 1) {
        int x = (t >= off) ? sh[t - off] : 0;
        __syncthreads();
        sh[t] += x;
        __syncthreads();
    }
    if (t < NB_SCAN) g_bsum[t] = sh[t] - v;
}

__global__ void k_scan3(int E) {
    int i = blockIdx.x * blockDim.x + threadIdx.x;
    if (i < N_NODES) {
        int v = g_rp[i] + g_bsum[i >> 8];
        g_rp[i]   = v;
        g_wptr[i] = v;
    }
    if (i == 0) g_rp[N_NODES] = E;
}

// fill: 4 independent edges per thread, src-only 4B payload
__global__ void k_fill(const int* __restrict__ src, const int* __restrict__ dst, int E) {
    int e0 = (blockIdx.x * blockDim.x + threadIdx.x) * 4;
    if (e0 + 3 < E) {
        int4 s4 = *(const int4*)(src + e0);
        int4 d4 = *(const int4*)(dst + e0);
        int p0 = atomicAdd(&g_wptr[d4.x], 1);
        int p1 = atomicAdd(&g_wptr[d4.y], 1);
        int p2 = atomicAdd(&g_wptr[d4.z], 1);
        int p3 = atomicAdd(&g_wptr[d4.w], 1);
        g_esrc[p0] = s4.x;
        g_esrc[p1] = s4.y;
        g_esrc[p2] = s4.z;
        g_esrc[p3] = s4.w;
    } else {
        for (int e = e0; e < E; ++e) {
            int pos = atomicAdd(&g_wptr[dst[e]], 1);
            g_esrc[pos] = src[e];
        }
    }
}

// ---------------- GEMM1: h1[N,64] = x[N,128] @ W1[128,64] -> fp16 --------
#define XT_STRIDE 132
__global__ void __launch_bounds__(256) k_gemm1(const float* __restrict__ x,
                                               const float* __restrict__ W) {
    __shared__ float xs_t[32 * XT_STRIDE];
    __shared__ float ws[32 * 64];
    const int t    = threadIdx.x;
    const int row0 = blockIdx.x * 128;
    const int tx8  = (t & 7) * 8;
    const int ty4  = (t >> 3) * 4;

    unsigned long long acc[4][4];
#pragma unroll
    for (int r = 0; r < 4; ++r)
#pragma unroll
        for (int j = 0; j < 4; ++j) acc[r][j] = 0ull;

    for (int kc = 0; kc < 128; kc += 32) {
        __syncthreads();
        {
            const float4* Wv = (const float4*)(W + kc * 64);
            float4* wsv = (float4*)ws;
            wsv[t]       = Wv[t];
            wsv[t + 256] = Wv[t + 256];
        }
#pragma unroll
        for (int i = 0; i < 4; ++i) {
            int idx = t + i * 256;
            int r = idx >> 3;
            int q = idx & 7;
            float4 v;
            if (row0 + r < N_NODES)
                v = *(const float4*)(x + (size_t)(row0 + r) * IN_C + kc + q * 4);
            else
                v = make_float4(0.f, 0.f, 0.f, 0.f);
            xs_t[(q * 4 + 0) * XT_STRIDE + r] = v.x;
            xs_t[(q * 4 + 1) * XT_STRIDE + r] = v.y;
            xs_t[(q * 4 + 2) * XT_STRIDE + r] = v.z;
            xs_t[(q * 4 + 3) * XT_STRIDE + r] = v.w;
        }
        __syncthreads();

#pragma unroll 8
        for (int k = 0; k < 32; ++k) {
            float4 av = *(const float4*)&xs_t[k * XT_STRIDE + ty4];
            ulonglong2 b0 = *(const ulonglong2*)&ws[k * 64 + tx8];
            ulonglong2 b1 = *(const ulonglong2*)&ws[k * 64 + tx8 + 4];
            unsigned long long pa[4];
            asm("mov.b64 %0, {%1,%1};" : "=l"(pa[0]) : "f"(av.x));
            asm("mov.b64 %0, {%1,%1};" : "=l"(pa[1]) : "f"(av.y));
            asm("mov.b64 %0, {%1,%1};" : "=l"(pa[2]) : "f"(av.z));
            asm("mov.b64 %0, {%1,%1};" : "=l"(pa[3]) : "f"(av.w));
#pragma unroll
            for (int r = 0; r < 4; ++r) {
                asm("fma.rn.f32x2 %0, %1, %2, %0;" : "+l"(acc[r][0]) : "l"(pa[r]), "l"(b0.x));
                asm("fma.rn.f32x2 %0, %1, %2, %0;" : "+l"(acc[r][1]) : "l"(pa[r]), "l"(b0.y));
                asm("fma.rn.f32x2 %0, %1, %2, %0;" : "+l"(acc[r][2]) : "l"(pa[r]), "l"(b1.x));
                asm("fma.rn.f32x2 %0, %1, %2, %0;" : "+l"(acc[r][3]) : "l"(pa[r]), "l"(b1.y));
            }
        }
    }

#pragma unroll
    for (int r = 0; r < 4; ++r) {
        int row = row0 + ty4 + r;
        if (row < N_NODES) {
            float o[8];
#pragma unroll
            for (int j = 0; j < 4; ++j)
                asm("mov.b64 {%0,%1}, %2;" : "=f"(o[2 * j]), "=f"(o[2 * j + 1]) : "l"(acc[r][j]));
            unsigned u[4];
#pragma unroll
            for (int j = 0; j < 4; ++j) {
                __half2 hh = __floats2half2_rn(o[2 * j], o[2 * j + 1]);
                u[j] = *(unsigned*)&hh;
            }
            *(uint4*)&g_h1h[(size_t)row * 32 + (t & 7) * 4] =
                make_uint4(u[0], u[1], u[2], u[3]);
        }
    }
}

// ---------------- aggregate layer 1: full warp/node, unroll 4x int4 ------
// out = relu(b1 + dinv_d^2*h1[n] + dinv_d * sum dinv_s*h1[s]) -> fp16
__global__ void __launch_bounds__(256) k_agg1(const float* __restrict__ b1) {
    int node = blockIdx.x * 8 + (threadIdx.x >> 5);
    if (node >= N_NODES) return;
    int lane = threadIdx.x & 31;
    int beg = g_rp[node], end = g_rp[node + 1];
    float dv = g_dinv[node];

    float ax = 0.f, ay = 0.f;
    int j = beg;
    for (; j < end && (j & 3); ++j) {             // peel to 16B-aligned j
        int s = g_esrc[j];
        float w = g_dinv[s];
        unsigned v = g_h1h[(unsigned)s * 32u + lane];
        float2 f = __half22float2(*(__half2*)&v);
        ax += w * f.x; ay += w * f.y;
    }
    for (; j + 7 < end; j += 8) {
        int4 sA = *(const int4*)&g_esrc[j];
        int4 sB = *(const int4*)&g_esrc[j + 4];
        float w0 = g_dinv[sA.x], w1 = g_dinv[sA.y];
        float w2 = g_dinv[sA.z], w3 = g_dinv[sA.w];
        float w4 = g_dinv[sB.x], w5 = g_dinv[sB.y];
        float w6 = g_dinv[sB.z], w7 = g_dinv[sB.w];
        unsigned v0 = g_h1h[(unsigned)sA.x * 32u + lane];
        unsigned v1 = g_h1h[(unsigned)sA.y * 32u + lane];
        unsigned v2 = g_h1h[(unsigned)sA.z * 32u + lane];
        unsigned v3 = g_h1h[(unsigned)sA.w * 32u + lane];
        unsigned v4 = g_h1h[(unsigned)sB.x * 32u + lane];
        unsigned v5 = g_h1h[(unsigned)sB.y * 32u + lane];
        unsigned v6 = g_h1h[(unsigned)sB.z * 32u + lane];
        unsigned v7 = g_h1h[(unsigned)sB.w * 32u + lane];
        float2 f0 = __half22float2(*(__half2*)&v0);
        float2 f1 = __half22float2(*(__half2*)&v1);
        float2 f2 = __half22float2(*(__half2*)&v2);
        float2 f3 = __half22float2(*(__half2*)&v3);
        float2 f4 = __half22float2(*(__half2*)&v4);
        float2 f5 = __half22float2(*(__half2*)&v5);
        float2 f6 = __half22float2(*(__half2*)&v6);
        float2 f7 = __half22float2(*(__half2*)&v7);
        ax += w0 * f0.x + w1 * f1.x + w2 * f2.x + w3 * f3.x
            + w4 * f4.x + w5 * f5.x + w6 * f6.x + w7 * f7.x;
        ay += w0 * f0.y + w1 * f1.y + w2 * f2.y + w3 * f3.y
            + w4 * f4.y + w5 * f5.y + w6 * f6.y + w7 * f7.y;
    }
    for (; j + 3 < end; j += 4) {
        int4 sA = *(const int4*)&g_esrc[j];
        float w0 = g_dinv[sA.x], w1 = g_dinv[sA.y];
        float w2 = g_dinv[sA.z], w3 = g_dinv[sA.w];
        unsigned v0 = g_h1h[(unsigned)sA.x * 32u + lane];
        unsigned v1 = g_h1h[(unsigned)sA.y * 32u + lane];
        unsigned v2 = g_h1h[(unsigned)sA.z * 32u + lane];
        unsigned v3 = g_h1h[(unsigned)sA.w * 32u + lane];
        float2 f0 = __half22float2(*(__half2*)&v0);
        float2 f1 = __half22float2(*(__half2*)&v1);
        float2 f2 = __half22float2(*(__half2*)&v2);
        float2 f3 = __half22float2(*(__half2*)&v3);
        ax += w0 * f0.x + w1 * f1.x + w2 * f2.x + w3 * f3.x;
        ay += w0 * f0.y + w1 * f1.y + w2 * f2.y + w3 * f3.y;
    }
    for (; j < end; ++j) {
        int s = g_esrc[j];
        float w = g_dinv[s];
        unsigned v = g_h1h[(unsigned)s * 32u + lane];
        float2 f = __half22float2(*(__half2*)&v);
        ax += w * f.x; ay += w * f.y;
    }

    unsigned sp = g_h1h[(unsigned)node * 32u + lane];
    float2 sv = __half22float2(*(__half2*)&sp);
    float2 bb = *(const float2*)&b1[lane * 2];
    float dd = dv * dv;
    ax = bb.x + sv.x * dd + dv * ax;
    ay = bb.y + sv.y * dd + dv * ay;

    __half2 hh = __floats2half2_rn(fmaxf(ax, 0.f), fmaxf(ay, 0.f));
    g_o1h[(unsigned)node * 32u + lane] = *(unsigned*)&hh;
}

// ---------------- GEMM2: h2[N,32] = o1[N,64] @ W2[64,32] -> fp16 ---------
__global__ void __launch_bounds__(256) k_gemm2(const float* __restrict__ W) {
    __shared__ float xs[64 * 64];
    __shared__ float ws[64 * 32];
    const int tid  = threadIdx.x;
    const int row0 = blockIdx.x * 64;

    const float4* Wv  = (const float4*)W;
    float4*       wsv = (float4*)ws;
#pragma unroll
    for (int i = 0; i < 2; ++i) wsv[tid + i * 256] = Wv[tid + i * 256];

    int nrows = N_NODES - row0; if (nrows > 64) nrows = 64;
    for (int i = tid; i < nrows * 8; i += 256) {
        int r = i >> 3, q = i & 7;
        uint4 v = *(const uint4*)&g_o1h[(size_t)(row0 + r) * 32 + q * 4];
        float2 f0 = __half22float2(*(__half2*)&v.x);
        float2 f1 = __half22float2(*(__half2*)&v.y);
        float2 f2 = __half22float2(*(__half2*)&v.z);
        float2 f3 = __half22float2(*(__half2*)&v.w);
        float* p = &xs[r * 64 + q * 8];
        *(float4*)p       = make_float4(f0.x, f0.y, f1.x, f1.y);
        *(float4*)(p + 4) = make_float4(f2.x, f2.y, f3.x, f3.y);
    }
    __syncthreads();

    const int tx = tid & 7;
    const int ty = tid >> 3;
    const int c  = tx * 4;
    float acc[2][4] = {};
#pragma unroll 4
    for (int k = 0; k < 64; ++k) {
        float4 b = *(const float4*)&ws[k * 32 + c];
#pragma unroll
        for (int i = 0; i < 2; ++i) {
            float a = xs[(ty * 2 + i) * 64 + k];
            acc[i][0] += a * b.x; acc[i][1] += a * b.y;
            acc[i][2] += a * b.z; acc[i][3] += a * b.w;
        }
    }
#pragma unroll
    for (int i = 0; i < 2; ++i) {
        int r = row0 + ty * 2 + i;
        if (r < N_NODES) {
            __half2 h0 = __floats2half2_rn(acc[i][0], acc[i][1]);
            __half2 h1 = __floats2half2_rn(acc[i][2], acc[i][3]);
            *(uint2*)&g_h2h[(size_t)r * 16 + tx * 2] =
                make_uint2(*(unsigned*)&h0, *(unsigned*)&h1);
        }
    }
}

// ---------------- aggregate layer 2 (half-warp/edge, unroll 2) -> out ----
__global__ void __launch_bounds__(256) k_agg2(const float* __restrict__ b2,
                                              float* __restrict__ out) {
    int node = blockIdx.x * 8 + (threadIdx.x >> 5);
    if (node >= N_NODES) return;
    int lane = threadIdx.x & 31;
    int c  = lane & 15;
    int eo = lane >> 4;

    int beg = g_rp[node], end = g_rp[node + 1];
    float ax = 0.f, ay = 0.f;

    int j = beg + eo;
    for (; j + 3 < end; j += 4) {
        int s0 = g_esrc[j];
        int s1 = g_esrc[j + 2];
        float w0 = g_dinv[s0];
        float w1 = g_dinv[s1];
        unsigned v0 = g_h2h[(unsigned)s0 * 16u + c];
        unsigned v1 = g_h2h[(unsigned)s1 * 16u + c];
        float2 f0 = __half22float2(*(__half2*)&v0);
        float2 f1 = __half22float2(*(__half2*)&v1);
        ax += w0 * f0.x + w1 * f1.x;
        ay += w0 * f0.y + w1 * f1.y;
    }
    for (; j < end; j += 2) {
        int s = g_esrc[j];
        float w = g_dinv[s];
        unsigned v = g_h2h[(unsigned)s * 16u + c];
        float2 f = __half22float2(*(__half2*)&v);
        ax += w * f.x; ay += w * f.y;
    }

    ax += __shfl_xor_sync(0xffffffffu, ax, 16);
    ay += __shfl_xor_sync(0xffffffffu, ay, 16);

    if (eo == 0) {
        float dv = g_dinv[node];
        float dd = dv * dv;
        unsigned sp = g_h2h[(unsigned)node * 16u + c];
        float2 sv = __half22float2(*(__half2*)&sp);
        float2 bb = *(const float2*)&b2[c * 2];
        ax = bb.x + sv.x * dd + dv * ax;
        ay = bb.y + sv.y * dd + dv * ay;
        *(float2*)&out[(size_t)node * OUT_C + c * 2] = make_float2(ax, ay);
    }
}

// ---------------- launch: strictly serial, proven order ------------------
extern "C" void kernel_launch(void* const* d_in, const int* in_sizes, int n_in,
                              void* d_out, int out_size) {
    const float* x  = (const float*)d_in[0];
    const int*   ei = (const int*)  d_in[1];
    const float* W1 = (const float*)d_in[2];
    const float* b1 = (const float*)d_in[3];
    const float* W2 = (const float*)d_in[4];
    const float* b2 = (const float*)d_in[5];
    float*       out = (float*)d_out;

    const int E   = in_sizes[1] / 2;
    const int* src = ei;
    const int* dst = ei + E;

    k_zero <<<(N_NODES + 255) / 256, 256>>>();
    k_count<<<(E / 4 + 255) / 256, 256>>>(dst, E);
    k_scan1<<<NB_SCAN, 256>>>();
    k_scan2<<<1, 512>>>();
    k_scan3<<<(N_NODES + 255) / 256, 256>>>(E);
    k_fill <<<(E / 4 + 255) / 256, 256>>>(src, dst, E);

    k_gemm1<<<(N_NODES + 127) / 128, 256>>>(x, W1);
    k_agg1 <<<(N_NODES + 7) / 8, 256>>>(b1);

    k_gemm2<<<(N_NODES + 63) / 64, 256>>>(W2);
    k_agg2 <<<(N_NODES + 7) / 8, 256>>>(b2, out);
}

// round 10
// speedup vs baseline: 2.2606x; 1.0077x over previous
#include <cuda_runtime.h>
#include <cuda_fp16.h>
#include <cstdint>

#define N_NODES 100000
#define IN_C    128
#define HID_C   64
#define OUT_C   32
#define E_MAX   1600000
#define NB_SCAN ((N_NODES + 255) / 256)   // 391

// ---------------- scratch ----------------
__device__ float g_dinv[N_NODES];
__device__ int   g_cnt[N_NODES];
__device__ int   g_rp[N_NODES + 1];
__device__ int   g_wptr[N_NODES];
__device__ int   g_bsum[NB_SCAN];
__device__ float2 g_epk[E_MAX];                       // (src bits, weight)
__device__ unsigned g_h1h[(size_t)N_NODES * 32];      // h1 fp16x2 (64 ch)
__device__ unsigned g_o1h[(size_t)N_NODES * 32];      // relu(agg1) fp16x2 (64 ch)
__device__ unsigned g_h2h[(size_t)N_NODES * 16];      // h2 fp16x2 (32 ch)

// ---------------- degree / CSR ----------------
__global__ void k_zero() {
    int i = blockIdx.x * blockDim.x + threadIdx.x;
    if (i < N_NODES) g_cnt[i] = 0;
}

__global__ void k_count(const int* __restrict__ dst, int E) {
    int e0 = (blockIdx.x * blockDim.x + threadIdx.x) * 4;
    if (e0 + 3 < E) {
        int4 d4 = *(const int4*)(dst + e0);
        atomicAdd(&g_cnt[d4.x], 1);
        atomicAdd(&g_cnt[d4.y], 1);
        atomicAdd(&g_cnt[d4.z], 1);
        atomicAdd(&g_cnt[d4.w], 1);
    } else {
        for (int e = e0; e < E; ++e) atomicAdd(&g_cnt[dst[e]], 1);
    }
}

__global__ void k_scan1() {
    __shared__ int sh[256];
    int t = threadIdx.x;
    int i = blockIdx.x * 256 + t;
    int v = (i < N_NODES) ? g_cnt[i] : 0;
    if (i < N_NODES) g_dinv[i] = rsqrtf(1.0f + (float)v);
    sh[t] = v;
    __syncthreads();
#pragma unroll
    for (int off = 1; off < 256; off <<= 1) {
        int x = (t >= off) ? sh[t - off] : 0;
        __syncthreads();
        sh[t] += x;
        __syncthreads();
    }
    if (i < N_NODES) g_rp[i] = sh[t] - v;
    if (t == 255) g_bsum[blockIdx.x] = sh[255];
}

__global__ void k_scan2() {
    __shared__ int sh[512];
    int t = threadIdx.x;
    int v = (t < NB_SCAN) ? g_bsum[t] : 0;
    sh[t] = v;
    __syncthreads();
#pragma unroll
    for (int off = 1; off < 512; off <<= 1) {
        int x = (t >= off) ? sh[t - off] : 0;
        __syncthreads();
        sh[t] += x;
        __syncthreads();
    }
    if (t < NB_SCAN) g_bsum[t] = sh[t] - v;
}

__global__ void k_scan3(int E) {
    int i = blockIdx.x * blockDim.x + threadIdx.x;
    if (i < N_NODES) {
        int v = g_rp[i] + g_bsum[i >> 8];
        g_rp[i]   = v;
        g_wptr[i] = v;
    }
    if (i == 0) g_rp[N_NODES] = E;
}

// fill: 4 independent edges/thread, packed (src, weight) payload
__global__ void k_fill(const int* __restrict__ src, const int* __restrict__ dst, int E) {
    int e0 = (blockIdx.x * blockDim.x + threadIdx.x) * 4;
    if (e0 + 3 < E) {
        int4 s4 = *(const int4*)(src + e0);
        int4 d4 = *(const int4*)(dst + e0);
        float w0 = g_dinv[s4.x] * g_dinv[d4.x];
        float w1 = g_dinv[s4.y] * g_dinv[d4.y];
        float w2 = g_dinv[s4.z] * g_dinv[d4.z];
        float w3 = g_dinv[s4.w] * g_dinv[d4.w];
        int p0 = atomicAdd(&g_wptr[d4.x], 1);
        int p1 = atomicAdd(&g_wptr[d4.y], 1);
        int p2 = atomicAdd(&g_wptr[d4.z], 1);
        int p3 = atomicAdd(&g_wptr[d4.w], 1);
        g_epk[p0] = make_float2(__int_as_float(s4.x), w0);
        g_epk[p1] = make_float2(__int_as_float(s4.y), w1);
        g_epk[p2] = make_float2(__int_as_float(s4.z), w2);
        g_epk[p3] = make_float2(__int_as_float(s4.w), w3);
    } else {
        for (int e = e0; e < E; ++e) {
            int s = src[e], d = dst[e];
            float w = g_dinv[s] * g_dinv[d];
            int pos = atomicAdd(&g_wptr[d], 1);
            g_epk[pos] = make_float2(__int_as_float(s), w);
        }
    }
}

// ---------------- GEMM1: h1[N,64] = x[N,128] @ W1[128,64] -> fp16 --------
#define XT_STRIDE 132
__global__ void __launch_bounds__(256) k_gemm1(const float* __restrict__ x,
                                               const float* __restrict__ W) {
    __shared__ float xs_t[32 * XT_STRIDE];
    __shared__ float ws[32 * 64];
    const int t    = threadIdx.x;
    const int row0 = blockIdx.x * 128;
    const int tx8  = (t & 7) * 8;
    const int ty4  = (t >> 3) * 4;

    unsigned long long acc[4][4];
#pragma unroll
    for (int r = 0; r < 4; ++r)
#pragma unroll
        for (int j = 0; j < 4; ++j) acc[r][j] = 0ull;

    for (int kc = 0; kc < 128; kc += 32) {
        __syncthreads();
        {
            const float4* Wv = (const float4*)(W + kc * 64);
            float4* wsv = (float4*)ws;
            wsv[t]       = Wv[t];
            wsv[t + 256] = Wv[t + 256];
        }
#pragma unroll
        for (int i = 0; i < 4; ++i) {
            int idx = t + i * 256;
            int r = idx >> 3;
            int q = idx & 7;
            float4 v;
            if (row0 + r < N_NODES)
                v = *(const float4*)(x + (size_t)(row0 + r) * IN_C + kc + q * 4);
            else
                v = make_float4(0.f, 0.f, 0.f, 0.f);
            xs_t[(q * 4 + 0) * XT_STRIDE + r] = v.x;
            xs_t[(q * 4 + 1) * XT_STRIDE + r] = v.y;
            xs_t[(q * 4 + 2) * XT_STRIDE + r] = v.z;
            xs_t[(q * 4 + 3) * XT_STRIDE + r] = v.w;
        }
        __syncthreads();

#pragma unroll 8
        for (int k = 0; k < 32; ++k) {
            float4 av = *(const float4*)&xs_t[k * XT_STRIDE + ty4];
            ulonglong2 b0 = *(const ulonglong2*)&ws[k * 64 + tx8];
            ulonglong2 b1 = *(const ulonglong2*)&ws[k * 64 + tx8 + 4];
            unsigned long long pa[4];
            asm("mov.b64 %0, {%1,%1};" : "=l"(pa[0]) : "f"(av.x));
            asm("mov.b64 %0, {%1,%1};" : "=l"(pa[1]) : "f"(av.y));
            asm("mov.b64 %0, {%1,%1};" : "=l"(pa[2]) : "f"(av.z));
            asm("mov.b64 %0, {%1,%1};" : "=l"(pa[3]) : "f"(av.w));
#pragma unroll
            for (int r = 0; r < 4; ++r) {
                asm("fma.rn.f32x2 %0, %1, %2, %0;" : "+l"(acc[r][0]) : "l"(pa[r]), "l"(b0.x));
                asm("fma.rn.f32x2 %0, %1, %2, %0;" : "+l"(acc[r][1]) : "l"(pa[r]), "l"(b0.y));
                asm("fma.rn.f32x2 %0, %1, %2, %0;" : "+l"(acc[r][2]) : "l"(pa[r]), "l"(b1.x));
                asm("fma.rn.f32x2 %0, %1, %2, %0;" : "+l"(acc[r][3]) : "l"(pa[r]), "l"(b1.y));
            }
        }
    }

#pragma unroll
    for (int r = 0; r < 4; ++r) {
        int row = row0 + ty4 + r;
        if (row < N_NODES) {
            float o[8];
#pragma unroll
            for (int j = 0; j < 4; ++j)
                asm("mov.b64 {%0,%1}, %2;" : "=f"(o[2 * j]), "=f"(o[2 * j + 1]) : "l"(acc[r][j]));
            unsigned u[4];
#pragma unroll
            for (int j = 0; j < 4; ++j) {
                __half2 hh = __floats2half2_rn(o[2 * j], o[2 * j + 1]);
                u[j] = *(unsigned*)&hh;
            }
            *(uint4*)&g_h1h[(size_t)row * 32 + (t & 7) * 4] =
                make_uint4(u[0], u[1], u[2], u[3]);
        }
    }
}

// ---------------- aggregate layer 1: full warp/node, unroll 8 ------------
__global__ void __launch_bounds__(256) k_agg1(const float* __restrict__ b1) {
    int node = blockIdx.x * 8 + (threadIdx.x >> 5);
    if (node >= N_NODES) return;
    int lane = threadIdx.x & 31;
    int beg = g_rp[node], end = g_rp[node + 1];
    float d = g_dinv[node];
    float dd = d * d;

    unsigned sp = g_h1h[(unsigned)node * 32u + lane];
    float2 sv = __half22float2(*(__half2*)&sp);
    float2 bb = *(const float2*)&b1[lane * 2];
    float ax = bb.x + sv.x * dd;
    float ay = bb.y + sv.y * dd;

    int j = beg;
    if ((j & 1) && j < end) {
        float2 p = g_epk[j];
        unsigned v = g_h1h[(unsigned)__float_as_int(p.x) * 32u + lane];
        float2 f = __half22float2(*(__half2*)&v);
        ax += p.y * f.x; ay += p.y * f.y;
        ++j;
    }
    for (; j + 7 < end; j += 8) {
        float4 e0 = *(const float4*)&g_epk[j];
        float4 e1 = *(const float4*)&g_epk[j + 2];
        float4 e2 = *(const float4*)&g_epk[j + 4];
        float4 e3 = *(const float4*)&g_epk[j + 6];
        unsigned v0 = g_h1h[(unsigned)__float_as_int(e0.x) * 32u + lane];
        unsigned v1 = g_h1h[(unsigned)__float_as_int(e0.z) * 32u + lane];
        unsigned v2 = g_h1h[(unsigned)__float_as_int(e1.x) * 32u + lane];
        unsigned v3 = g_h1h[(unsigned)__float_as_int(e1.z) * 32u + lane];
        unsigned v4 = g_h1h[(unsigned)__float_as_int(e2.x) * 32u + lane];
        unsigned v5 = g_h1h[(unsigned)__float_as_int(e2.z) * 32u + lane];
        unsigned v6 = g_h1h[(unsigned)__float_as_int(e3.x) * 32u + lane];
        unsigned v7 = g_h1h[(unsigned)__float_as_int(e3.z) * 32u + lane];
        float2 f0 = __half22float2(*(__half2*)&v0);
        float2 f1 = __half22float2(*(__half2*)&v1);
        float2 f2 = __half22float2(*(__half2*)&v2);
        float2 f3 = __half22float2(*(__half2*)&v3);
        float2 f4 = __half22float2(*(__half2*)&v4);
        float2 f5 = __half22float2(*(__half2*)&v5);
        float2 f6 = __half22float2(*(__half2*)&v6);
        float2 f7 = __half22float2(*(__half2*)&v7);
        ax += e0.y * f0.x + e0.w * f1.x + e1.y * f2.x + e1.w * f3.x
            + e2.y * f4.x + e2.w * f5.x + e3.y * f6.x + e3.w * f7.x;
        ay += e0.y * f0.y + e0.w * f1.y + e1.y * f2.y + e1.w * f3.y
            + e2.y * f4.y + e2.w * f5.y + e3.y * f6.y + e3.w * f7.y;
    }
    for (; j + 1 < end; j += 2) {
        float4 e0 = *(const float4*)&g_epk[j];
        unsigned v0 = g_h1h[(unsigned)__float_as_int(e0.x) * 32u + lane];
        unsigned v1 = g_h1h[(unsigned)__float_as_int(e0.z) * 32u + lane];
        float2 f0 = __half22float2(*(__half2*)&v0);
        float2 f1 = __half22float2(*(__half2*)&v1);
        ax += e0.y * f0.x + e0.w * f1.x;
        ay += e0.y * f0.y + e0.w * f1.y;
    }
    if (j < end) {
        float2 p = g_epk[j];
        unsigned v = g_h1h[(unsigned)__float_as_int(p.x) * 32u + lane];
        float2 f = __half22float2(*(__half2*)&v);
        ax += p.y * f.x; ay += p.y * f.y;
    }

    __half2 hh = __floats2half2_rn(fmaxf(ax, 0.f), fmaxf(ay, 0.f));
    g_o1h[(unsigned)node * 32u + lane] = *(unsigned*)&hh;
}

// ---------------- GEMM2: h2[N,32] = o1[N,64] @ W2[64,32] -> fp16 ---------
__global__ void __launch_bounds__(256) k_gemm2(const float* __restrict__ W) {
    __shared__ float xs[64 * 64];
    __shared__ float ws[64 * 32];
    const int tid  = threadIdx.x;
    const int row0 = blockIdx.x * 64;

    const float4* Wv  = (const float4*)W;
    float4*       wsv = (float4*)ws;
#pragma unroll
    for (int i = 0; i < 2; ++i) wsv[tid + i * 256] = Wv[tid + i * 256];

    int nrows = N_NODES - row0; if (nrows > 64) nrows = 64;
    for (int i = tid; i < nrows * 8; i += 256) {
        int r = i >> 3, q = i & 7;
        uint4 v = *(const uint4*)&g_o1h[(size_t)(row0 + r) * 32 + q * 4];
        float2 f0 = __half22float2(*(__half2*)&v.x);
        float2 f1 = __half22float2(*(__half2*)&v.y);
        float2 f2 = __half22float2(*(__half2*)&v.z);
        float2 f3 = __half22float2(*(__half2*)&v.w);
        float* p = &xs[r * 64 + q * 8];
        *(float4*)p       = make_float4(f0.x, f0.y, f1.x, f1.y);
        *(float4*)(p + 4) = make_float4(f2.x, f2.y, f3.x, f3.y);
    }
    __syncthreads();

    const int tx = tid & 7;
    const int ty = tid >> 3;
    const int c  = tx * 4;
    float acc[2][4] = {};
#pragma unroll 4
    for (int k = 0; k < 64; ++k) {
        float4 b = *(const float4*)&ws[k * 32 + c];
#pragma unroll
        for (int i = 0; i < 2; ++i) {
            float a = xs[(ty * 2 + i) * 64 + k];
            acc[i][0] += a * b.x; acc[i][1] += a * b.y;
            acc[i][2] += a * b.z; acc[i][3] += a * b.w;
        }
    }
#pragma unroll
    for (int i = 0; i < 2; ++i) {
        int r = row0 + ty * 2 + i;
        if (r < N_NODES) {
            __half2 h0 = __floats2half2_rn(acc[i][0], acc[i][1]);
            __half2 h1 = __floats2half2_rn(acc[i][2], acc[i][3]);
            *(uint2*)&g_h2h[(size_t)r * 16 + tx * 2] =
                make_uint2(*(unsigned*)&h0, *(unsigned*)&h1);
        }
    }
}

// ---------------- aggregate layer 2 (half-warp/edge, unroll 2) -> out ----
__global__ void __launch_bounds__(256) k_agg2(const float* __restrict__ b2,
                                              float* __restrict__ out) {
    int node = blockIdx.x * 8 + (threadIdx.x >> 5);
    if (node >= N_NODES) return;
    int lane = threadIdx.x & 31;
    int c  = lane & 15;
    int eo = lane >> 4;

    int beg = g_rp[node], end = g_rp[node + 1];
    float ax = 0.f, ay = 0.f;

    int j = beg + eo;
    for (; j + 3 < end; j += 4) {
        float2 p0 = g_epk[j];
        float2 p1 = g_epk[j + 2];
        unsigned v0 = g_h2h[(unsigned)__float_as_int(p0.x) * 16u + c];
        unsigned v1 = g_h2h[(unsigned)__float_as_int(p1.x) * 16u + c];
        float2 f0 = __half22float2(*(__half2*)&v0);
        float2 f1 = __half22float2(*(__half2*)&v1);
        ax += p0.y * f0.x + p1.y * f1.x;
        ay += p0.y * f0.y + p1.y * f1.y;
    }
    for (; j < end; j += 2) {
        float2 p = g_epk[j];
        unsigned v = g_h2h[(unsigned)__float_as_int(p.x) * 16u + c];
        float2 f = __half22float2(*(__half2*)&v);
        ax += p.y * f.x; ay += p.y * f.y;
    }

    ax += __shfl_xor_sync(0xffffffffu, ax, 16);
    ay += __shfl_xor_sync(0xffffffffu, ay, 16);

    if (eo == 0) {
        float d = g_dinv[node];
        float dd = d * d;
        unsigned sp = g_h2h[(unsigned)node * 16u + c];
        float2 sv = __half22float2(*(__half2*)&sp);
        float2 bb = *(const float2*)&b2[c * 2];
        ax += bb.x + sv.x * dd;
        ay += bb.y + sv.y * dd;
        *(float2*)&out[(size_t)node * OUT_C + c * 2] = make_float2(ax, ay);
    }
}

// ---------------- launch: serial; gemm1 in slot 4 for ncu capture --------
extern "C" void kernel_launch(void* const* d_in, const int* in_sizes, int n_in,
                              void* d_out, int out_size) {
    const float* x  = (const float*)d_in[0];
    const int*   ei = (const int*)  d_in[1];
    const float* W1 = (const float*)d_in[2];
    const float* b1 = (const float*)d_in[3];
    const float* W2 = (const float*)d_in[4];
    const float* b2 = (const float*)d_in[5];
    float*       out = (float*)d_out;

    const int E   = in_sizes[1] / 2;
    const int* src = ei;
    const int* dst = ei + E;

    k_zero <<<(N_NODES + 255) / 256, 256>>>();
    k_count<<<(E / 4 + 255) / 256, 256>>>(dst, E);
    k_scan1<<<NB_SCAN, 256>>>();
    k_gemm1<<<(N_NODES + 127) / 128, 256>>>(x, W1);   // slot 4: profiled launch
    k_scan2<<<1, 512>>>();
    k_scan3<<<(N_NODES + 255) / 256, 256>>>(E);
    k_fill <<<(E / 4 + 255) / 256, 256>>>(src, dst, E);

    k_agg1 <<<(N_NODES + 7) / 8, 256>>>(b1);
    k_gemm2<<<(N_NODES + 63) / 64, 256>>>(W2);
    k_agg2 <<<(N_NODES + 7) / 8, 256>>>(b2, out);
}

// round 11
// speedup vs baseline: 2.7265x; 1.2061x over previous
#include <cuda_runtime.h>
#include <cuda_fp16.h>
#include <cstdint>

#define N_NODES 100000
#define IN_C    128
#define HID_C   64
#define OUT_C   32
#define E_MAX   1600000
#define NB_SCAN ((N_NODES + 255) / 256)   // 391

// ---------------- scratch ----------------
__device__ float g_dinv[N_NODES];
__device__ int   g_cnt[N_NODES];
__device__ int   g_rp[N_NODES + 1];
__device__ int   g_wptr[N_NODES];
__device__ int   g_bsum[NB_SCAN];
__device__ float2 g_epk[E_MAX];                       // (src bits, weight)
__device__ unsigned g_h1h[(size_t)N_NODES * 32];      // h1 fp16x2 (64 ch)
__device__ unsigned g_o1h[(size_t)N_NODES * 32];      // relu(agg1) fp16x2 (64 ch)
__device__ unsigned g_h2h[(size_t)N_NODES * 16];      // h2 fp16x2 (32 ch)

// ---------------- degree / CSR ----------------
__global__ void k_zero() {
    int i = blockIdx.x * blockDim.x + threadIdx.x;
    if (i < N_NODES) g_cnt[i] = 0;
}

__global__ void k_count(const int* __restrict__ dst, int E) {
    int e0 = (blockIdx.x * blockDim.x + threadIdx.x) * 4;
    if (e0 + 3 < E) {
        int4 d4 = *(const int4*)(dst + e0);
        atomicAdd(&g_cnt[d4.x], 1);
        atomicAdd(&g_cnt[d4.y], 1);
        atomicAdd(&g_cnt[d4.z], 1);
        atomicAdd(&g_cnt[d4.w], 1);
    } else {
        for (int e = e0; e < E; ++e) atomicAdd(&g_cnt[dst[e]], 1);
    }
}

__global__ void k_scan1() {
    __shared__ int sh[256];
    int t = threadIdx.x;
    int i = blockIdx.x * 256 + t;
    int v = (i < N_NODES) ? g_cnt[i] : 0;
    if (i < N_NODES) g_dinv[i] = rsqrtf(1.0f + (float)v);
    sh[t] = v;
    __syncthreads();
#pragma unroll
    for (int off = 1; off < 256; off <<= 1) {
        int x = (t >= off) ? sh[t - off] : 0;
        __syncthreads();
        sh[t] += x;
        __syncthreads();
    }
    if (i < N_NODES) g_rp[i] = sh[t] - v;
    if (t == 255) g_bsum[blockIdx.x] = sh[255];
}

__global__ void k_scan2() {
    __shared__ int sh[512];
    int t = threadIdx.x;
    int v = (t < NB_SCAN) ? g_bsum[t] : 0;
    sh[t] = v;
    __syncthreads();
#pragma unroll
    for (int off = 1; off < 512; off <<= 1) {
        int x = (t >= off) ? sh[t - off] : 0;
        __syncthreads();
        sh[t] += x;
        __syncthreads();
    }
    if (t < NB_SCAN) g_bsum[t] = sh[t] - v;
}

__global__ void k_scan3(int E) {
    int i = blockIdx.x * blockDim.x + threadIdx.x;
    if (i < N_NODES) {
        int v = g_rp[i] + g_bsum[i >> 8];
        g_rp[i]   = v;
        g_wptr[i] = v;
    }
    if (i == 0) g_rp[N_NODES] = E;
}

// fill: 4 independent edges/thread, packed (src, weight) payload
__global__ void k_fill(const int* __restrict__ src, const int* __restrict__ dst, int E) {
    int e0 = (blockIdx.x * blockDim.x + threadIdx.x) * 4;
    if (e0 + 3 < E) {
        int4 s4 = *(const int4*)(src + e0);
        int4 d4 = *(const int4*)(dst + e0);
        float w0 = g_dinv[s4.x] * g_dinv[d4.x];
        float w1 = g_dinv[s4.y] * g_dinv[d4.y];
        float w2 = g_dinv[s4.z] * g_dinv[d4.z];
        float w3 = g_dinv[s4.w] * g_dinv[d4.w];
        int p0 = atomicAdd(&g_wptr[d4.x], 1);
        int p1 = atomicAdd(&g_wptr[d4.y], 1);
        int p2 = atomicAdd(&g_wptr[d4.z], 1);
        int p3 = atomicAdd(&g_wptr[d4.w], 1);
        g_epk[p0] = make_float2(__int_as_float(s4.x), w0);
        g_epk[p1] = make_float2(__int_as_float(s4.y), w1);
        g_epk[p2] = make_float2(__int_as_float(s4.z), w2);
        g_epk[p3] = make_float2(__int_as_float(s4.w), w3);
    } else {
        for (int e = e0; e < E; ++e) {
            int s = src[e], d = dst[e];
            float w = g_dinv[s] * g_dinv[d];
            int pos = atomicAdd(&g_wptr[d], 1);
            g_epk[pos] = make_float2(__int_as_float(s), w);
        }
    }
}

// ---------------- GEMM1 (tensor core): h1 = x @ W1 -> fp16 ---------------
// Block tile M=128, N=64, K chunked by 64. 8 warps, warp tile m16 x n64.
// mma.sync.m16n8k16 f16.f32. xs: [128 rows][72 halves] per chunk (pad->no
// bank conflicts: 72 halves = 36 words, 36 mod 32 = 4). ws: [64 n][136 k].
#define XS_STR 72     // halves per row (64 k + 8 pad)
#define WS_STR 136    // halves per n row (128 k + 8 pad)
__global__ void __launch_bounds__(256) k_gemm1(const float* __restrict__ x,
                                               const float* __restrict__ W) {
    __shared__ __half xs[128 * XS_STR];   // 18.4 KB
    __shared__ __half ws[64 * WS_STR];    // 17.4 KB
    const int t = threadIdx.x;
    const int row0 = blockIdx.x * 128;
    const int w    = t >> 5;
    const int lane = t & 31;
    const int g    = lane >> 2;          // 0..7
    const int tq   = lane & 3;           // 0..3
    const int arow = w * 16;

    // load W1 [128][64] -> ws[n][k] fp16 (one-time, transposed)
#pragma unroll
    for (int i = 0; i < 8; ++i) {
        int idx = t + i * 256;           // float4 index, 0..2047
        int k = idx >> 4;                // 0..127
        int q = idx & 15;                // n-group of 4
        float4 v = ((const float4*)W)[idx];
        ws[(q * 4 + 0) * WS_STR + k] = __float2half(v.x);
        ws[(q * 4 + 1) * WS_STR + k] = __float2half(v.y);
        ws[(q * 4 + 2) * WS_STR + k] = __float2half(v.z);
        ws[(q * 4 + 3) * WS_STR + k] = __float2half(v.w);
    }

    float acc[8][4];
#pragma unroll
    for (int i = 0; i < 8; ++i)
#pragma unroll
        for (int j = 0; j < 4; ++j) acc[i][j] = 0.f;

    for (int kc = 0; kc < 128; kc += 64) {
        __syncthreads();
        // load x chunk [128 rows][64 k] -> fp16 (zero-fill OOB rows)
#pragma unroll
        for (int i = 0; i < 8; ++i) {
            int idx = t + i * 256;       // 0..2047
            int r = idx >> 4;            // 0..127
            int q = idx & 15;            // float4 within 64-col chunk
            float4 v;
            if (row0 + r < N_NODES)
                v = *(const float4*)(x + (size_t)(row0 + r) * IN_C + kc + q * 4);
            else
                v = make_float4(0.f, 0.f, 0.f, 0.f);
            __half2 h0 = __floats2half2_rn(v.x, v.y);
            __half2 h1 = __floats2half2_rn(v.z, v.w);
            *(__half2*)&xs[r * XS_STR + q * 4]     = h0;
            *(__half2*)&xs[r * XS_STR + q * 4 + 2] = h1;
        }
        __syncthreads();

#pragma unroll
        for (int ks = 0; ks < 64; ks += 16) {
            unsigned A0, A1, A2, A3;
            const int c0 = ks + tq * 2;
            A0 = *(const unsigned*)&xs[(arow + g)     * XS_STR + c0];
            A1 = *(const unsigned*)&xs[(arow + g + 8) * XS_STR + c0];
            A2 = *(const unsigned*)&xs[(arow + g)     * XS_STR + c0 + 8];
            A3 = *(const unsigned*)&xs[(arow + g + 8) * XS_STR + c0 + 8];
            const int kb = kc + ks + tq * 2;
#pragma unroll
            for (int i = 0; i < 8; ++i) {
                unsigned B0 = *(const unsigned*)&ws[(i * 8 + g) * WS_STR + kb];
                unsigned B1 = *(const unsigned*)&ws[(i * 8 + g) * WS_STR + kb + 8];
                asm volatile(
                    "mma.sync.aligned.m16n8k16.row.col.f32.f16.f16.f32 "
                    "{%0,%1,%2,%3},{%4,%5,%6,%7},{%8,%9},{%0,%1,%2,%3};"
                    : "+f"(acc[i][0]), "+f"(acc[i][1]), "+f"(acc[i][2]), "+f"(acc[i][3])
                    : "r"(A0), "r"(A1), "r"(A2), "r"(A3), "r"(B0), "r"(B1));
            }
        }
    }

    // store: c0,c1 -> row (arow+g), cols (tq*2, tq*2+1) of n-tile i
    int r0 = row0 + arow + g;
    int r1 = r0 + 8;
#pragma unroll
    for (int i = 0; i < 8; ++i) {
        if (r0 < N_NODES) {
            __half2 h = __floats2half2_rn(acc[i][0], acc[i][1]);
            g_h1h[(size_t)r0 * 32 + i * 4 + tq] = *(unsigned*)&h;
        }
        if (r1 < N_NODES) {
            __half2 h = __floats2half2_rn(acc[i][2], acc[i][3]);
            g_h1h[(size_t)r1 * 32 + i * 4 + tq] = *(unsigned*)&h;
        }
    }
}

// ---------------- aggregate layer 1: full warp/node, unroll 8 ------------
__global__ void __launch_bounds__(256) k_agg1(const float* __restrict__ b1) {
    int node = blockIdx.x * 8 + (threadIdx.x >> 5);
    if (node >= N_NODES) return;
    int lane = threadIdx.x & 31;
    int beg = g_rp[node], end = g_rp[node + 1];
    float d = g_dinv[node];
    float dd = d * d;

    unsigned sp = g_h1h[(unsigned)node * 32u + lane];
    float2 sv = __half22float2(*(__half2*)&sp);
    float2 bb = *(const float2*)&b1[lane * 2];
    float ax = bb.x + sv.x * dd;
    float ay = bb.y + sv.y * dd;

    int j = beg;
    if ((j & 1) && j < end) {
        float2 p = g_epk[j];
        unsigned v = g_h1h[(unsigned)__float_as_int(p.x) * 32u + lane];
        float2 f = __half22float2(*(__half2*)&v);
        ax += p.y * f.x; ay += p.y * f.y;
        ++j;
    }
    for (; j + 7 < end; j += 8) {
        float4 e0 = *(const float4*)&g_epk[j];
        float4 e1 = *(const float4*)&g_epk[j + 2];
        float4 e2 = *(const float4*)&g_epk[j + 4];
        float4 e3 = *(const float4*)&g_epk[j + 6];
        unsigned v0 = g_h1h[(unsigned)__float_as_int(e0.x) * 32u + lane];
        unsigned v1 = g_h1h[(unsigned)__float_as_int(e0.z) * 32u + lane];
        unsigned v2 = g_h1h[(unsigned)__float_as_int(e1.x) * 32u + lane];
        unsigned v3 = g_h1h[(unsigned)__float_as_int(e1.z) * 32u + lane];
        unsigned v4 = g_h1h[(unsigned)__float_as_int(e2.x) * 32u + lane];
        unsigned v5 = g_h1h[(unsigned)__float_as_int(e2.z) * 32u + lane];
        unsigned v6 = g_h1h[(unsigned)__float_as_int(e3.x) * 32u + lane];
        unsigned v7 = g_h1h[(unsigned)__float_as_int(e3.z) * 32u + lane];
        float2 f0 = __half22float2(*(__half2*)&v0);
        float2 f1 = __half22float2(*(__half2*)&v1);
        float2 f2 = __half22float2(*(__half2*)&v2);
        float2 f3 = __half22float2(*(__half2*)&v3);
        float2 f4 = __half22float2(*(__half2*)&v4);
        float2 f5 = __half22float2(*(__half2*)&v5);
        float2 f6 = __half22float2(*(__half2*)&v6);
        float2 f7 = __half22float2(*(__half2*)&v7);
        ax += e0.y * f0.x + e0.w * f1.x + e1.y * f2.x + e1.w * f3.x
            + e2.y * f4.x + e2.w * f5.x + e3.y * f6.x + e3.w * f7.x;
        ay += e0.y * f0.y + e0.w * f1.y + e1.y * f2.y + e1.w * f3.y
            + e2.y * f4.y + e2.w * f5.y + e3.y * f6.y + e3.w * f7.y;
    }
    for (; j + 1 < end; j += 2) {
        float4 e0 = *(const float4*)&g_epk[j];
        unsigned v0 = g_h1h[(unsigned)__float_as_int(e0.x) * 32u + lane];
        unsigned v1 = g_h1h[(unsigned)__float_as_int(e0.z) * 32u + lane];
        float2 f0 = __half22float2(*(__half2*)&v0);
        float2 f1 = __half22float2(*(__half2*)&v1);
        ax += e0.y * f0.x + e0.w * f1.x;
        ay += e0.y * f0.y + e0.w * f1.y;
    }
    if (j < end) {
        float2 p = g_epk[j];
        unsigned v = g_h1h[(unsigned)__float_as_int(p.x) * 32u + lane];
        float2 f = __half22float2(*(__half2*)&v);
        ax += p.y * f.x; ay += p.y * f.y;
    }

    __half2 hh = __floats2half2_rn(fmaxf(ax, 0.f), fmaxf(ay, 0.f));
    g_o1h[(unsigned)node * 32u + lane] = *(unsigned*)&hh;
}

// ---------------- GEMM2: h2[N,32] = o1[N,64] @ W2[64,32] -> fp16 ---------
__global__ void __launch_bounds__(256) k_gemm2(const float* __restrict__ W) {
    __shared__ float xs[64 * 64];
    __shared__ float ws[64 * 32];
    const int tid  = threadIdx.x;
    const int row0 = blockIdx.x * 64;

    const float4* Wv  = (const float4*)W;
    float4*       wsv = (float4*)ws;
#pragma unroll
    for (int i = 0; i < 2; ++i) wsv[tid + i * 256] = Wv[tid + i * 256];

    int nrows = N_NODES - row0; if (nrows > 64) nrows = 64;
    for (int i = tid; i < nrows * 8; i += 256) {
        int r = i >> 3, q = i & 7;
        uint4 v = *(const uint4*)&g_o1h[(size_t)(row0 + r) * 32 + q * 4];
        float2 f0 = __half22float2(*(__half2*)&v.x);
        float2 f1 = __half22float2(*(__half2*)&v.y);
        float2 f2 = __half22float2(*(__half2*)&v.z);
        float2 f3 = __half22float2(*(__half2*)&v.w);
        float* p = &xs[r * 64 + q * 8];
        *(float4*)p       = make_float4(f0.x, f0.y, f1.x, f1.y);
        *(float4*)(p + 4) = make_float4(f2.x, f2.y, f3.x, f3.y);
    }
    __syncthreads();

    const int tx = tid & 7;
    const int ty = tid >> 3;
    const int c  = tx * 4;
    float acc[2][4] = {};
#pragma unroll 4
    for (int k = 0; k < 64; ++k) {
        float4 b = *(const float4*)&ws[k * 32 + c];
#pragma unroll
        for (int i = 0; i < 2; ++i) {
            float a = xs[(ty * 2 + i) * 64 + k];
            acc[i][0] += a * b.x; acc[i][1] += a * b.y;
            acc[i][2] += a * b.z; acc[i][3] += a * b.w;
        }
    }
#pragma unroll
    for (int i = 0; i < 2; ++i) {
        int r = row0 + ty * 2 + i;
        if (r < N_NODES) {
            __half2 h0 = __floats2half2_rn(acc[i][0], acc[i][1]);
            __half2 h1 = __floats2half2_rn(acc[i][2], acc[i][3]);
            *(uint2*)&g_h2h[(size_t)r * 16 + tx * 2] =
                make_uint2(*(unsigned*)&h0, *(unsigned*)&h1);
        }
    }
}

// ---------------- aggregate layer 2 (half-warp/edge, unroll 2) -> out ----
__global__ void __launch_bounds__(256) k_agg2(const float* __restrict__ b2,
                                              float* __restrict__ out) {
    int node = blockIdx.x * 8 + (threadIdx.x >> 5);
    if (node >= N_NODES) return;
    int lane = threadIdx.x & 31;
    int c  = lane & 15;
    int eo = lane >> 4;

    int beg = g_rp[node], end = g_rp[node + 1];
    float ax = 0.f, ay = 0.f;

    int j = beg + eo;
    for (; j + 3 < end; j += 4) {
        float2 p0 = g_epk[j];
        float2 p1 = g_epk[j + 2];
        unsigned v0 = g_h2h[(unsigned)__float_as_int(p0.x) * 16u + c];
        unsigned v1 = g_h2h[(unsigned)__float_as_int(p1.x) * 16u + c];
        float2 f0 = __half22float2(*(__half2*)&v0);
        float2 f1 = __half22float2(*(__half2*)&v1);
        ax += p0.y * f0.x + p1.y * f1.x;
        ay += p0.y * f0.y + p1.y * f1.y;
    }
    for (; j < end; j += 2) {
        float2 p = g_epk[j];
        unsigned v = g_h2h[(unsigned)__float_as_int(p.x) * 16u + c];
        float2 f = __half22float2(*(__half2*)&v);
        ax += p.y * f.x; ay += p.y * f.y;
    }

    ax += __shfl_xor_sync(0xffffffffu, ax, 16);
    ay += __shfl_xor_sync(0xffffffffu, ay, 16);

    if (eo == 0) {
        float d = g_dinv[node];
        float dd = d * d;
        unsigned sp = g_h2h[(unsigned)node * 16u + c];
        float2 sv = __half22float2(*(__half2*)&sp);
        float2 bb = *(const float2*)&b2[c * 2];
        ax += bb.x + sv.x * dd;
        ay += bb.y + sv.y * dd;
        *(float2*)&out[(size_t)node * OUT_C + c * 2] = make_float2(ax, ay);
    }
}

// ---------------- launch: serial; gemm1 in slot 4 for ncu capture --------
extern "C" void kernel_launch(void* const* d_in, const int* in_sizes, int n_in,
                              void* d_out, int out_size) {
    const float* x  = (const float*)d_in[0];
    const int*   ei = (const int*)  d_in[1];
    const float* W1 = (const float*)d_in[2];
    const float* b1 = (const float*)d_in[3];
    const float* W2 = (const float*)d_in[4];
    const float* b2 = (const float*)d_in[5];
    float*       out = (float*)d_out;

    const int E   = in_sizes[1] / 2;
    const int* src = ei;
    const int* dst = ei + E;

    k_zero <<<(N_NODES + 255) / 256, 256>>>();
    k_count<<<(E / 4 + 255) / 256, 256>>>(dst, E);
    k_scan1<<<NB_SCAN, 256>>>();
    k_gemm1<<<(N_NODES + 127) / 128, 256>>>(x, W1);   // slot 4: profiled launch
    k_scan2<<<1, 512>>>();
    k_scan3<<<(N_NODES + 255) / 256, 256>>>(E);
    k_fill <<<(E / 4 + 255) / 256, 256>>>(src, dst, E);

    k_agg1 <<<(N_NODES + 7) / 8, 256>>>(b1);
    k_gemm2<<<(N_NODES + 63) / 64, 256>>>(W2);
    k_agg2 <<<(N_NODES + 7) / 8, 256>>>(b2, out);
}